// round 12
// baseline (speedup 1.0000x reference)
#include <cuda_runtime.h>
#include <cuda_bf16.h>
#include <cstdint>
#include <cstddef>

// Problem constants
#define BB   256
#define KK   16
#define HH   512
#define DD   64
#define KN   48          // 3 mats x 16 k
#define NCH  8           // 512 / 64 h-chunks

typedef unsigned long long ull;

// Transposed bf16 split planes: xT[dp][b][h], dp = d*2 + plane (0=hi,1=lo)
__device__ __align__(16) __nv_bfloat16 g_xT[(size_t)2 * DD * BB * HH];   // 33.5 MB
__device__ __align__(16) __nv_bfloat16 g_vT[(size_t)2 * DD * KN * HH];   // 6.3 MB
// reduced logits (bias included): [b][mat][k][d] : 3 MB
__device__ __align__(16) float g_red[(size_t)BB * 3 * KK * DD];

// ---------------- PTX helpers ----------------
__device__ __forceinline__ void cp_async16(uint32_t dst, const void* src) {
    asm volatile("cp.async.ca.shared.global [%0], [%1], 16;\n" ::"r"(dst), "l"(src) : "memory");
}
__device__ __forceinline__ void cp_commit() {
    asm volatile("cp.async.commit_group;\n" ::: "memory");
}
template <int N>
__device__ __forceinline__ void cp_wait() {
    asm volatile("cp.async.wait_group %0;\n" ::"n"(N) : "memory");
}
__device__ __forceinline__ void ldsm_x4(uint32_t* r, uint32_t addr) {
    asm volatile("ldmatrix.sync.aligned.m8n8.x4.shared.b16 {%0,%1,%2,%3}, [%4];"
        : "=r"(r[0]), "=r"(r[1]), "=r"(r[2]), "=r"(r[3]) : "r"(addr));
}
__device__ __forceinline__ void mma_bf16(float* d, const uint32_t* a, const uint32_t* b) {
    asm volatile(
        "mma.sync.aligned.m16n8k16.row.col.f32.bf16.bf16.f32 "
        "{%0,%1,%2,%3}, {%4,%5,%6,%7}, {%8,%9}, {%0,%1,%2,%3};"
        : "+f"(d[0]), "+f"(d[1]), "+f"(d[2]), "+f"(d[3])
        : "r"(a[0]), "r"(a[1]), "r"(a[2]), "r"(a[3]), "r"(b[0]), "r"(b[1]));
}

// ================= Transpose + bf16 split =================
// tile: 8 rows x 64 h x 64 d fp32 in smem, padded layout s[(r*64+d)*65 + h]
template <int NR>
__device__ __forceinline__ void trans_tile(
    float* sm, const float* const* rowSrc, __nv_bfloat16* dstBase,
    int h0, int dstRowStrideRows, int rowGlobBase)
{
    const int tid = threadIdx.x;
#pragma unroll 4
    for (int idx = tid; idx < NR * 64 * 16; idx += 256) {
        const int dq = idx & 15;
        const int h = (idx >> 4) & 63;
        const int r = idx >> 10;
        const float4 v = *(const float4*)(rowSrc[r] + (size_t)(h0 + h) * DD + dq * 4);
        float* base = sm + h;
        base[((size_t)(r * 64 + dq * 4 + 0)) * 65] = v.x;
        base[((size_t)(r * 64 + dq * 4 + 1)) * 65] = v.y;
        base[((size_t)(r * 64 + dq * 4 + 2)) * 65] = v.z;
        base[((size_t)(r * 64 + dq * 4 + 3)) * 65] = v.w;
    }
    __syncthreads();

    const int w = tid >> 5;
    const int l = tid & 31;
    const int nRows = 64 * NR;
#pragma unroll 2
    for (int row = w; row < nRows; row += 8) {
        const int d = row >> 3;
        const int r = row & (NR - 1);
        const float* rp = sm + ((size_t)(r * 64 + d)) * 65;
        const float v0 = rp[2 * l];          // scalar loads: 65-stride rows are
        const float v1 = rp[2 * l + 1];      // only 4B-aligned (float2 would trap)
        const __nv_bfloat16 h0b = __float2bfloat16_rn(v0);
        const __nv_bfloat16 h1b = __float2bfloat16_rn(v1);
        const float l0 = v0 - __bfloat162float(h0b);
        const float l1 = v1 - __bfloat162float(h1b);
        __nv_bfloat162 hi2; hi2.x = h0b; hi2.y = h1b;
        const __nv_bfloat162 lo2 = __floats2bfloat162_rn(l0, l1);
        const int rowGlob = rowGlobBase + r;
        __nv_bfloat162* pHi = (__nv_bfloat162*)(dstBase +
            ((size_t)(2 * d) * dstRowStrideRows + rowGlob) * HH + h0) + l;
        __nv_bfloat162* pLo = (__nv_bfloat162*)(dstBase +
            ((size_t)(2 * d + 1) * dstRowStrideRows + rowGlob) * HH + h0) + l;
        *pHi = hi2;
        *pLo = lo2;
    }
}

__global__ void __launch_bounds__(256) k_transX(const float* __restrict__ x)
{
    extern __shared__ float sm[];
    __shared__ const float* rowSrc[8];
    const int b0 = blockIdx.x * 8;
    const int h0 = blockIdx.y * 64;
    if (threadIdx.x < 8)
        rowSrc[threadIdx.x] = x + (size_t)(b0 + threadIdx.x) * (HH * DD);
    __syncthreads();
    trans_tile<8>(sm, rowSrc, g_xT, h0, BB, b0);
}

__global__ void __launch_bounds__(256) k_transV(
    const float* __restrict__ Va, const float* __restrict__ Vm, const float* __restrict__ Vs)
{
    extern __shared__ float sm[];
    __shared__ const float* rowSrc[8];
    const int kn0 = blockIdx.x * 8;
    const int h0 = blockIdx.y * 64;
    if (threadIdx.x < 8) {
        const int kn = kn0 + threadIdx.x;
        const int mat = kn >> 4;
        const int k = kn & 15;
        const float* Vp = (mat == 0) ? Va : ((mat == 1) ? Vm : Vs);
        rowSrc[threadIdx.x] = Vp + (size_t)k * (HH * DD);
    }
    __syncthreads();
    trans_tile<8>(sm, rowSrc, g_vT, h0, KN, kn0);
}

// ================= mma.sync GEMM: per-d D[128b x 48kn] = sum_h x*V (3-product split) =====
// smem stage: Ahi[128x64] | Alo | Bhi[48x64] | Blo, rows padded to 144B (72 bf16)
#define AROW_B  144
#define PL_A    (128 * AROW_B)                 // 18432
#define B_OFF   (2 * PL_A)                     // 36864
#define PL_B    (48 * AROW_B)                  // 6912
#define STB     (B_OFF + 2 * PL_B)             // 50688
#define NSTG    3
#define BIAS_OFF (NSTG * STB)                  // 152064
#define GSMEM   (BIAS_OFF + 256)

__device__ __forceinline__ void issue_chunk_m(
    uint32_t sbase, int stage, int c, int tid, int dCTA, int bhalf)
{
    const uint32_t stB = sbase + (uint32_t)stage * STB;
    const char* xHi = (const char*)(g_xT + ((size_t)(2 * dCTA) * BB + bhalf * 128) * HH) + c * 128;
    const char* xLo = (const char*)(g_xT + ((size_t)(2 * dCTA + 1) * BB + bhalf * 128) * HH) + c * 128;
    const char* vHi = (const char*)(g_vT + ((size_t)(2 * dCTA) * KN) * HH) + c * 128;
    const char* vLo = (const char*)(g_vT + ((size_t)(2 * dCTA + 1) * KN) * HH) + c * 128;
#pragma unroll
    for (int i = 0; i < 22; i++) {
        const int j = tid + i * 128;
        const char* src;
        uint32_t tileOff;
        int jj;
        if (i < 8)       { jj = j;        src = xHi; tileOff = 0; }
        else if (i < 16) { jj = j - 1024; src = xLo; tileOff = PL_A; }
        else if (i < 19) { jj = j - 2048; src = vHi; tileOff = B_OFF; }
        else             { jj = j - 2432; src = vLo; tileOff = B_OFF + PL_B; }
        const int row = jj >> 3;
        const int q = jj & 7;
        cp_async16(stB + tileOff + (uint32_t)row * AROW_B + (uint32_t)q * 16u,
                   src + (size_t)row * (HH * 2) + q * 16);
    }
    cp_commit();
}

__global__ void __launch_bounds__(128) k_gemm_mma(
    const float* __restrict__ ba, const float* __restrict__ bm, const float* __restrict__ bs)
{
    extern __shared__ char smc[];
    const uint32_t sbase = (uint32_t)__cvta_generic_to_shared(smc);
    const int tid = threadIdx.x;
    const int w = tid >> 5;
    const int l = tid & 31;
    const int dCTA = blockIdx.x;
    const int bhalf = blockIdx.y;

    // bias[n] for this d
    if (tid < KN) {
        const int mat = tid >> 4;
        const int k = tid & 15;
        const float* bp = (mat == 0) ? ba : ((mat == 1) ? bm : bs);
        *(float*)(smc + BIAS_OFF + tid * 4) = bp[k * DD + dCTA];
    }

    // ldmatrix per-lane offsets
    const int g = l >> 3;
    // A x4: mat0 rows0-7 col0 | mat1 rows8-15 col0 | mat2 rows0-7 col16 | mat3 rows8-15 col16
    const int aRow = (g & 1) * 8 + (l & 7);
    const int aColB = (g >> 1) * 16;
    // B x4 (non-trans; smem rows are [n][k] = col-major B):
    // mat0 nt0 k-half0 | mat1 nt0 k-half1 | mat2 nt1 k-half0 | mat3 nt1 k-half1
    const int bRow = (g >> 1) * 8 + (l & 7);
    const int bColB = (g & 1) * 16;
    uint32_t aOff[2][2], bOff[2][3];
#pragma unroll
    for (int p = 0; p < 2; p++) {
#pragma unroll
        for (int mt = 0; mt < 2; mt++)
            aOff[p][mt] = (uint32_t)(p * PL_A + (w * 32 + mt * 16 + aRow) * AROW_B + aColB);
#pragma unroll
        for (int np = 0; np < 3; np++)
            bOff[p][np] = (uint32_t)(B_OFF + p * PL_B + (np * 16 + bRow) * AROW_B + bColB);
    }

    float acc[2][6][4];
#pragma unroll
    for (int mt = 0; mt < 2; mt++)
#pragma unroll
        for (int nt = 0; nt < 6; nt++)
#pragma unroll
            for (int j = 0; j < 4; j++) acc[mt][nt][j] = 0.f;

    issue_chunk_m(sbase, 0, 0, tid, dCTA, bhalf);
    issue_chunk_m(sbase, 1, 1, tid, dCTA, bhalf);

    int stC = 0;
#pragma unroll 1
    for (int c = 0; c < NCH; c++) {
        if (c + 1 < NCH) { cp_wait<1>(); } else { cp_wait<0>(); }
        __syncthreads();
        if (c + 2 < NCH) {
            int stN = stC + 2; if (stN >= NSTG) stN -= NSTG;
            issue_chunk_m(sbase, stN, c + 2, tid, dCTA, bhalf);
        }

        const uint32_t stB = sbase + (uint32_t)stC * STB;
#pragma unroll
        for (int kk = 0; kk < 4; kk++) {
            uint32_t afr[2][2][4];
#pragma unroll
            for (int p = 0; p < 2; p++)
#pragma unroll
                for (int mt = 0; mt < 2; mt++)
                    ldsm_x4(afr[p][mt], stB + aOff[p][mt] + kk * 32);
            uint32_t bfr[2][6][2];
#pragma unroll
            for (int p = 0; p < 2; p++)
#pragma unroll
                for (int np = 0; np < 3; np++) {
                    uint32_t r4[4];
                    ldsm_x4(r4, stB + bOff[p][np] + kk * 32);   // NON-trans: [n][k] rows
                    bfr[p][2 * np][0] = r4[0]; bfr[p][2 * np][1] = r4[1];
                    bfr[p][2 * np + 1][0] = r4[2]; bfr[p][2 * np + 1][1] = r4[3];
                }
#pragma unroll
            for (int mt = 0; mt < 2; mt++)
#pragma unroll
                for (int nt = 0; nt < 6; nt++) {
                    mma_bf16(acc[mt][nt], afr[0][mt], bfr[0][nt]);   // hi*hi
                    mma_bf16(acc[mt][nt], afr[0][mt], bfr[1][nt]);   // hi*lo
                    mma_bf16(acc[mt][nt], afr[1][mt], bfr[0][nt]);   // lo*hi
                }
        }
        stC = stC + 1; if (stC == NSTG) stC = 0;
    }

    // epilogue: acc[mt][nt][j]: j0=(r,c) j1=(r,c+1) j2=(r+8,c) j3=(r+8,c+1)
    const float* bias = (const float*)(smc + BIAS_OFF);
#pragma unroll
    for (int mt = 0; mt < 2; mt++) {
#pragma unroll
        for (int half = 0; half < 2; half++) {
            const int b = bhalf * 128 + w * 32 + mt * 16 + (l >> 2) + half * 8;
            float* outb = g_red + (size_t)b * (KN * DD) + dCTA;
#pragma unroll
            for (int nt = 0; nt < 6; nt++) {
                const int n0 = nt * 8 + 2 * (l & 3);
                outb[(size_t)n0 * DD] = acc[mt][nt][half * 2 + 0] + bias[n0];
                outb[(size_t)(n0 + 1) * DD] = acc[mt][nt][half * 2 + 1] + bias[n0 + 1];
            }
        }
    }
}

// ---------------- Pass 2: softmax/logsumexp epilogue, sum over d ----------------
__global__ void __launch_bounds__(256) k_final(
    const float* __restrict__ iv, float* __restrict__ out)
{
    const int tx = threadIdx.x;                    // lane -> d-pair
    const int b = blockIdx.x * 8 + threadIdx.y;    // one warp per b

    float2 ea[16], mu[16], ls[16];

    const float2* __restrict__ rd = (const float2*)g_red;
    const size_t base = ((size_t)b * 3) * 512 + tx;  // float2 units; mat stride 512, k stride 32
#pragma unroll
    for (int k = 0; k < 16; k++) ea[k] = rd[base + (size_t)k * 32];
#pragma unroll
    for (int k = 0; k < 16; k++) mu[k] = rd[base + 512 + (size_t)k * 32];
#pragma unroll
    for (int k = 0; k < 16; k++) ls[k] = rd[base + 1024 + (size_t)k * 32];

    const float2 y2 = ((const float2*)iv)[b * 32 + tx];

    float contrib = 0.f;
    const float HL2PI = 0.91893853320467274178f;
#pragma unroll
    for (int comp = 0; comp < 2; comp++) {
        const float yv = comp ? y2.y : y2.x;
        float mA = -3.0e38f;
#pragma unroll
        for (int k = 0; k < 16; k++) {
            const float e = comp ? ea[k].y : ea[k].x;
            mA = fmaxf(mA, e);
        }
        float sA = 0.f;
#pragma unroll
        for (int k = 0; k < 16; k++) {
            const float e = comp ? ea[k].y : ea[k].x;
            sA += __expf(e - mA);
        }
        const float lseA = mA + __logf(sA);

        float t[16];
        float mT = -3.0e38f;
#pragma unroll
        for (int k = 0; k < 16; k++) {
            const float e = comp ? ea[k].y : ea[k].x;
            const float m = comp ? mu[k].y : mu[k].x;
            float s = comp ? ls[k].y : ls[k].x;
            s = fminf(fmaxf(s, -20.f), 20.f);       // clip log_sigma
            const float z = (yv - m) * __expf(-s);
            const float tt = -0.5f * z * z + e - s;
            t[k] = tt;
            mT = fmaxf(mT, tt);
        }
        float sP = 0.f;
#pragma unroll
        for (int k = 0; k < 16; k++) sP += __expf(t[k] - mT);
        contrib += mT + __logf(sP) - lseA - HL2PI;
    }

#pragma unroll
    for (int off = 16; off > 0; off >>= 1)
        contrib += __shfl_down_sync(0xffffffffu, contrib, off);
    if (tx == 0) out[b] = contrib;
}

// ---------------- launch ----------------
extern "C" void kernel_launch(void* const* d_in, const int* in_sizes, int n_in,
                              void* d_out, int out_size)
{
    (void)in_sizes; (void)n_in; (void)out_size;
    const float* x  = (const float*)d_in[0];
    const float* iv = (const float*)d_in[1];
    const float* Va = (const float*)d_in[2];
    const float* Vm = (const float*)d_in[3];
    const float* Vs = (const float*)d_in[4];
    const float* ba = (const float*)d_in[5];
    const float* bm = (const float*)d_in[6];
    const float* bs = (const float*)d_in[7];

    const int tSmem = 8 * 64 * 65 * 4 + 256;       // ~133 KB transpose staging
    cudaFuncSetAttribute(k_transX, cudaFuncAttributeMaxDynamicSharedMemorySize, tSmem);
    cudaFuncSetAttribute(k_transV, cudaFuncAttributeMaxDynamicSharedMemorySize, tSmem);
    cudaFuncSetAttribute(k_gemm_mma, cudaFuncAttributeMaxDynamicSharedMemorySize, GSMEM);

    k_transX<<<dim3(BB / 8, HH / 64), 256, tSmem>>>(x);
    k_transV<<<dim3(KN / 8, HH / 64), 256, tSmem>>>(Va, Vm, Vs);
    k_gemm_mma<<<dim3(DD, 2), 128, GSMEM>>>(ba, bm, bs);
    k_final<<<BB / 8, dim3(32, 8)>>>(iv, (float*)d_out);
}

// round 13
// speedup vs baseline: 1.4525x; 1.4525x over previous
#include <cuda_runtime.h>
#include <cuda_bf16.h>
#include <cstdint>
#include <cstddef>

// Problem constants
#define BB   256
#define KK   16
#define HH   512
#define DD   64
#define KN   48          // 3 mats x 16 k
#define HSPL 4           // h splits (grid.z)
#define NCH  8           // (512/4) / 16 h-chunks per CTA
#define HC   16          // h per chunk

// V transposed bf16 split planes: vT[dp][kn][h], dp = d*2 + plane (0=hi,1=lo)
__device__ __align__(16) __nv_bfloat16 g_vT[(size_t)2 * DD * KN * HH];   // 6.3 MB
// GEMM partials: [hs][d][kn][b] fp32 : 12.6 MB
__device__ __align__(16) float g_scratch[(size_t)HSPL * DD * KN * BB];
// reduced logits (bias included): [b][kn][d] : 3 MB
__device__ __align__(16) float g_red[(size_t)BB * KN * DD];

// ---------------- PTX helpers ----------------
__device__ __forceinline__ void cp_async16(uint32_t dst, const void* src) {
    asm volatile("cp.async.ca.shared.global [%0], [%1], 16;\n" ::"r"(dst), "l"(src) : "memory");
}
__device__ __forceinline__ void cp_commit() {
    asm volatile("cp.async.commit_group;\n" ::: "memory");
}
template <int N>
__device__ __forceinline__ void cp_wait() {
    asm volatile("cp.async.wait_group %0;\n" ::"n"(N) : "memory");
}
__device__ __forceinline__ void sts32(uint32_t addr, uint32_t v) {
    asm volatile("st.shared.b32 [%0], %1;\n" ::"r"(addr), "r"(v) : "memory");
}
__device__ __forceinline__ void ldsm_x4(uint32_t* r, uint32_t addr) {
    asm volatile("ldmatrix.sync.aligned.m8n8.x4.shared.b16 {%0,%1,%2,%3}, [%4];"
        : "=r"(r[0]), "=r"(r[1]), "=r"(r[2]), "=r"(r[3]) : "r"(addr));
}
__device__ __forceinline__ void mma_bf16(float* d, const uint32_t* a, const uint32_t* b) {
    asm volatile(
        "mma.sync.aligned.m16n8k16.row.col.f32.bf16.bf16.f32 "
        "{%0,%1,%2,%3}, {%4,%5,%6,%7}, {%8,%9}, {%0,%1,%2,%3};"
        : "+f"(d[0]), "+f"(d[1]), "+f"(d[2]), "+f"(d[3])
        : "r"(a[0]), "r"(a[1]), "r"(a[2]), "r"(a[3]), "r"(b[0]), "r"(b[1]));
}

// ================= transV: V -> vT[dp][kn][h] with bf16 hi/lo split =================
template <int NR>
__device__ __forceinline__ void trans_tile(
    float* sm, const float* const* rowSrc, __nv_bfloat16* dstBase,
    int h0, int dstRowStrideRows, int rowGlobBase)
{
    const int tid = threadIdx.x;
#pragma unroll 4
    for (int idx = tid; idx < NR * 64 * 16; idx += 256) {
        const int dq = idx & 15;
        const int h = (idx >> 4) & 63;
        const int r = idx >> 10;
        const float4 v = *(const float4*)(rowSrc[r] + (size_t)(h0 + h) * DD + dq * 4);
        float* base = sm + h;
        base[((size_t)(r * 64 + dq * 4 + 0)) * 65] = v.x;
        base[((size_t)(r * 64 + dq * 4 + 1)) * 65] = v.y;
        base[((size_t)(r * 64 + dq * 4 + 2)) * 65] = v.z;
        base[((size_t)(r * 64 + dq * 4 + 3)) * 65] = v.w;
    }
    __syncthreads();

    const int w = tid >> 5;
    const int l = tid & 31;
    const int nRows = 64 * NR;
#pragma unroll 2
    for (int row = w; row < nRows; row += 8) {
        const int d = row >> 3;
        const int r = row & (NR - 1);
        const float* rp = sm + ((size_t)(r * 64 + d)) * 65;
        const float v0 = rp[2 * l];          // scalar: 65-stride rows are 4B-aligned only
        const float v1 = rp[2 * l + 1];
        const __nv_bfloat16 h0b = __float2bfloat16_rn(v0);
        const __nv_bfloat16 h1b = __float2bfloat16_rn(v1);
        const float l0 = v0 - __bfloat162float(h0b);
        const float l1 = v1 - __bfloat162float(h1b);
        __nv_bfloat162 hi2; hi2.x = h0b; hi2.y = h1b;
        const __nv_bfloat162 lo2 = __floats2bfloat162_rn(l0, l1);
        const int rowGlob = rowGlobBase + r;
        __nv_bfloat162* pHi = (__nv_bfloat162*)(dstBase +
            ((size_t)(2 * d) * dstRowStrideRows + rowGlob) * HH + h0) + l;
        __nv_bfloat162* pLo = (__nv_bfloat162*)(dstBase +
            ((size_t)(2 * d + 1) * dstRowStrideRows + rowGlob) * HH + h0) + l;
        *pHi = hi2;
        *pLo = lo2;
    }
}

__global__ void __launch_bounds__(256) k_transV(
    const float* __restrict__ Va, const float* __restrict__ Vm, const float* __restrict__ Vs)
{
    extern __shared__ float sm[];
    __shared__ const float* rowSrc[8];
    const int kn0 = blockIdx.x * 8;
    const int h0 = blockIdx.y * 64;
    if (threadIdx.x < 8) {
        const int kn = kn0 + threadIdx.x;
        const int mat = kn >> 4;
        const int k = kn & 15;
        const float* Vp = (mat == 0) ? Va : ((mat == 1) ? Vm : Vs);
        rowSrc[threadIdx.x] = Vp + (size_t)k * (HH * DD);
    }
    __syncthreads();
    trans_tile<8>(sm, rowSrc, g_vT, h0, KN, kn0);
}

// ================= fused GEMM: D[48 kn][128 b] per (dq, bh, hs); A=V, B=x =================
// x tiles (B op):  8 planes (dd*2+p) of [128 b rows][16 h], row pitch 48B  -> 6144 B/tile
// V tiles (A op):  8 planes of [48 kn rows][16 h], row pitch 48B           -> 2304 B/tile
#define XT_PITCH 48
#define XT_BYTES (128 * 48)            // 6144
#define VT_BYTES (48 * 48)             // 2304
#define X_OFF    0
#define V_OFF    (8 * XT_BYTES)        // 49152
#define STGB     (V_OFF + 8 * VT_BYTES)  // 67584
#define NSTG     3
#define GSMEM    (NSTG * STGB)         // 202752

__device__ __forceinline__ void issue_V(uint32_t sbase, int stage, int c, int tid,
                                        int dq, int hs)
{
    const uint32_t stB = sbase + (uint32_t)stage * STGB + V_OFF;
    const int hglob = hs * 128 + c * HC;
#pragma unroll
    for (int i = 0; i < 3; i++) {
        const int idx = tid + i * 256;           // 768 = 8 tiles x 48 rows x 2 halves
        const int half = idx & 1;
        const int kn = (idx >> 1) % 48;
        const int t8 = idx / 96;                 // dd*2+p
        const __nv_bfloat16* src = g_vT + ((size_t)(dq * 8 + t8) * KN + kn) * HH
                                        + hglob + half * 8;
        cp_async16(stB + (uint32_t)t8 * VT_BYTES + (uint32_t)kn * XT_PITCH + half * 16u, src);
    }
    cp_commit();
}

__device__ __forceinline__ void xload(uint32_t sbase, int stage, int c, int tid,
                                      const float* __restrict__ x, int dq, int bh, int hs)
{
    const uint32_t stB = sbase + (uint32_t)stage * STGB + X_OFF;
#pragma unroll
    for (int s = 0; s < 4; s++) {
        const int u = tid + s * 256;             // 1024 = 128 b x 8 h-pairs
        const int hp = u & 7;
        const int bl = u >> 3;
        const int h = hs * 128 + c * HC + hp * 2;
        const float* p0 = x + ((size_t)(bh * 128 + bl) * HH + h) * DD + dq * 4;
        const float4 v0 = *(const float4*)p0;
        const float4 v1 = *(const float4*)(p0 + DD);
        const float f0[4] = {v0.x, v0.y, v0.z, v0.w};
        const float f1[4] = {v1.x, v1.y, v1.z, v1.w};
        const uint32_t dst0 = stB + (uint32_t)bl * XT_PITCH + (uint32_t)hp * 4u;
#pragma unroll
        for (int dd = 0; dd < 4; dd++) {
            const __nv_bfloat16 h0b = __float2bfloat16_rn(f0[dd]);
            const __nv_bfloat16 h1b = __float2bfloat16_rn(f1[dd]);
            __nv_bfloat162 hi2; hi2.x = h0b; hi2.y = h1b;
            const __nv_bfloat162 lo2 = __floats2bfloat162_rn(
                f0[dd] - __bfloat162float(h0b), f1[dd] - __bfloat162float(h1b));
            sts32(dst0 + (uint32_t)(dd * 2) * XT_BYTES, *(const uint32_t*)&hi2);
            sts32(dst0 + (uint32_t)(dd * 2 + 1) * XT_BYTES, *(const uint32_t*)&lo2);
        }
    }
}

__global__ void __launch_bounds__(256, 1) k_gemm_f(const float* __restrict__ x)
{
    extern __shared__ char smc[];
    const uint32_t sbase = (uint32_t)__cvta_generic_to_shared(smc);
    const int tid = threadIdx.x;
    const int w = tid >> 5;
    const int l = tid & 31;
    const int dq = blockIdx.x;                   // d quad 0..15
    const int bh = blockIdx.y;                   // b half 0..1
    const int hs = blockIdx.z;                   // h split 0..3
    const int dd = w >> 1;                       // warp's d within quad
    const int nh = w & 1;                        // warp's b-half-of-128 (64 each)

    // ldmatrix per-lane offsets (verified recipe from R12)
    const int g = l >> 3;
    const int aRow = (g & 1) * 8 + (l & 7);      // A (V): rows kn
    const int aColB = (g >> 1) * 16;
    const int bRow = (g >> 1) * 8 + (l & 7);     // B (x): rows b
    const int bColB = (g & 1) * 16;

    uint32_t aOff[2][3], bOff[2][4];
#pragma unroll
    for (int p = 0; p < 2; p++) {
#pragma unroll
        for (int mt = 0; mt < 3; mt++)
            aOff[p][mt] = (uint32_t)(V_OFF + (dd * 2 + p) * VT_BYTES
                                     + (mt * 16 + aRow) * XT_PITCH + aColB);
#pragma unroll
        for (int np = 0; np < 4; np++)
            bOff[p][np] = (uint32_t)(X_OFF + (dd * 2 + p) * XT_BYTES
                                     + (nh * 64 + np * 16 + bRow) * XT_PITCH + bColB);
    }

    float acc[3][8][4];
#pragma unroll
    for (int mt = 0; mt < 3; mt++)
#pragma unroll
        for (int nt = 0; nt < 8; nt++)
#pragma unroll
            for (int j = 0; j < 4; j++) acc[mt][nt][j] = 0.f;

    issue_V(sbase, 0, 0, tid, dq, hs);
    issue_V(sbase, 1, 1, tid, dq, hs);
    xload(sbase, 0, 0, tid, x, dq, bh, hs);

#pragma unroll 1
    for (int c = 0; c < NCH; c++) {
        const int stC = c % NSTG;
        if (c + 1 < NCH) { cp_wait<1>(); } else { cp_wait<0>(); }
        __syncthreads();
        if (c + 2 < NCH) issue_V(sbase, (c + 2) % NSTG, c + 2, tid, dq, hs);
        if (c + 1 < NCH) xload(sbase, (c + 1) % NSTG, c + 1, tid, x, dq, bh, hs);

        const uint32_t stB = sbase + (uint32_t)stC * STGB;
        uint32_t afr[2][3][4];
#pragma unroll
        for (int p = 0; p < 2; p++)
#pragma unroll
            for (int mt = 0; mt < 3; mt++)
                ldsm_x4(afr[p][mt], stB + aOff[p][mt]);
        uint32_t bfr[2][8][2];
#pragma unroll
        for (int p = 0; p < 2; p++)
#pragma unroll
            for (int np = 0; np < 4; np++) {
                uint32_t r4[4];
                ldsm_x4(r4, stB + bOff[p][np]);
                bfr[p][2 * np][0] = r4[0]; bfr[p][2 * np][1] = r4[1];
                bfr[p][2 * np + 1][0] = r4[2]; bfr[p][2 * np + 1][1] = r4[3];
            }
#pragma unroll
        for (int nt = 0; nt < 8; nt++)
#pragma unroll
            for (int mt = 0; mt < 3; mt++) {
                mma_bf16(acc[mt][nt], afr[0][mt], bfr[0][nt]);   // Vhi * xhi
                mma_bf16(acc[mt][nt], afr[0][mt], bfr[1][nt]);   // Vhi * xlo
                mma_bf16(acc[mt][nt], afr[1][mt], bfr[0][nt]);   // Vlo * xhi
            }
    }

    // store partials: scratch[hs][d][kn][b], float2 along b
    const int d = dq * 4 + dd;
    float2* scr2 = (float2*)g_scratch;
#pragma unroll
    for (int mt = 0; mt < 3; mt++) {
        const int kn = mt * 16 + (l >> 2);
#pragma unroll
        for (int nt = 0; nt < 8; nt++) {
            const int b = bh * 128 + nh * 64 + nt * 8 + 2 * (l & 3);
            const size_t i0 = ((((size_t)hs * DD + d) * KN + kn) * BB + b) >> 1;
            float2 v0; v0.x = acc[mt][nt][0]; v0.y = acc[mt][nt][1];
            float2 v1; v1.x = acc[mt][nt][2]; v1.y = acc[mt][nt][3];
            scr2[i0] = v0;
            scr2[i0 + (8 * BB >> 1)] = v1;       // kn + 8
        }
    }
}

// ================= transposing reduce over hs (+ bias): -> g_red[b][kn][d] ==============
__global__ void __launch_bounds__(256) k_reduce2(
    const float* __restrict__ ba, const float* __restrict__ bm, const float* __restrict__ bs)
{
    __shared__ float s[DD][17];
    const int t = threadIdx.x;
    const int b0 = blockIdx.x * 16;
    const int kn = blockIdx.y;

    const int bi = t & 15;
    const int dg = t >> 4;
#pragma unroll
    for (int j = 0; j < 4; j++) {
        const int d = dg + j * 16;
        float v = 0.f;
#pragma unroll
        for (int hsI = 0; hsI < HSPL; hsI++)
            v += g_scratch[(((size_t)hsI * DD + d) * KN + kn) * BB + b0 + bi];
        s[d][bi] = v;
    }
    __syncthreads();

    const int mat = kn >> 4;
    const float* bp = (mat == 0) ? ba : ((mat == 1) ? bm : bs);
    const int dw = t & 63;
    const int bj = t >> 6;
    const float biasv = bp[(kn & 15) * DD + dw];
#pragma unroll
    for (int j = 0; j < 4; j++) {
        const int bl = bj * 4 + j;
        g_red[((size_t)(b0 + bl) * KN + kn) * DD + dw] = s[dw][bl] + biasv;
    }
}

// ---------------- Pass 2: softmax/logsumexp epilogue, sum over d ----------------
__global__ void __launch_bounds__(64) k_final(
    const float* __restrict__ iv, float* __restrict__ out)
{
    const int tx = threadIdx.x;                    // lane -> d-pair
    const int b = blockIdx.x * 2 + threadIdx.y;    // one warp per b

    float2 ea[16], mu[16], ls[16];

    const float2* __restrict__ rd = (const float2*)g_red;
    const size_t base = (size_t)b * (KN * DD / 2) + tx;  // kn stride 32 float2
#pragma unroll
    for (int k = 0; k < 16; k++) ea[k] = rd[base + (size_t)k * 32];
#pragma unroll
    for (int k = 0; k < 16; k++) mu[k] = rd[base + 512 + (size_t)k * 32];
#pragma unroll
    for (int k = 0; k < 16; k++) ls[k] = rd[base + 1024 + (size_t)k * 32];

    const float2 y2 = ((const float2*)iv)[b * 32 + tx];

    float contrib = 0.f;
    const float HL2PI = 0.91893853320467274178f;
#pragma unroll
    for (int comp = 0; comp < 2; comp++) {
        const float yv = comp ? y2.y : y2.x;
        float mA = -3.0e38f;
#pragma unroll
        for (int k = 0; k < 16; k++) {
            const float e = comp ? ea[k].y : ea[k].x;
            mA = fmaxf(mA, e);
        }
        float sA = 0.f;
#pragma unroll
        for (int k = 0; k < 16; k++) {
            const float e = comp ? ea[k].y : ea[k].x;
            sA += __expf(e - mA);
        }
        const float lseA = mA + __logf(sA);

        float tt[16];
        float mT = -3.0e38f;
#pragma unroll
        for (int k = 0; k < 16; k++) {
            const float e = comp ? ea[k].y : ea[k].x;
            const float m = comp ? mu[k].y : mu[k].x;
            float sv = comp ? ls[k].y : ls[k].x;
            sv = fminf(fmaxf(sv, -20.f), 20.f);     // clip log_sigma
            const float z = (yv - m) * __expf(-sv);
            const float t1 = -0.5f * z * z + e - sv;
            tt[k] = t1;
            mT = fmaxf(mT, t1);
        }
        float sP = 0.f;
#pragma unroll
        for (int k = 0; k < 16; k++) sP += __expf(tt[k] - mT);
        contrib += mT + __logf(sP) - lseA - HL2PI;
    }

#pragma unroll
    for (int off = 16; off > 0; off >>= 1)
        contrib += __shfl_down_sync(0xffffffffu, contrib, off);
    if (tx == 0) out[b] = contrib;
}

// ---------------- launch ----------------
extern "C" void kernel_launch(void* const* d_in, const int* in_sizes, int n_in,
                              void* d_out, int out_size)
{
    (void)in_sizes; (void)n_in; (void)out_size;
    const float* x  = (const float*)d_in[0];
    const float* iv = (const float*)d_in[1];
    const float* Va = (const float*)d_in[2];
    const float* Vm = (const float*)d_in[3];
    const float* Vs = (const float*)d_in[4];
    const float* ba = (const float*)d_in[5];
    const float* bm = (const float*)d_in[6];
    const float* bs = (const float*)d_in[7];

    const int tSmem = 8 * 64 * 65 * 4 + 256;       // ~133 KB transpose staging
    cudaFuncSetAttribute(k_transV, cudaFuncAttributeMaxDynamicSharedMemorySize, tSmem);
    cudaFuncSetAttribute(k_gemm_f, cudaFuncAttributeMaxDynamicSharedMemorySize, GSMEM);

    k_transV<<<dim3(KN / 8, HH / 64), 256, tSmem>>>(Va, Vm, Vs);
    k_gemm_f<<<dim3(16, 2, HSPL), 256, GSMEM>>>(x);
    k_reduce2<<<dim3(BB / 16, KN), 256>>>(ba, bm, bs);
    k_final<<<BB / 2, dim3(32, 2)>>>(iv, (float*)d_out);
}

// round 14
// speedup vs baseline: 1.6486x; 1.1350x over previous
#include <cuda_runtime.h>
#include <cstdint>
#include <cstddef>

// Problem constants
#define BB   256
#define KK   16
#define HH   512
#define DD   64

// Pass-1 tiling
#define BT       16     // b per block
#define HSPLIT   8      // h splits (grid.y)
#define HRANGE   64     // h per block
#define HC       4      // h per smem chunk
#define NCHUNK   16     // HRANGE / HC
#define STAGES   3
#define NTHREADS 384    // 12 warps: 2 b-groups x 3 matrices x 2 k-halves

// smem chunk: 64 rows (16 x-rows + 48 V-rows) x (HC*64) floats = 16384 floats = 64KB
#define CHUNK_FLOATS 16384
#define CHUNK_BYTES  65536
#define ROW_BYTES    1024           // HC*DD*4 bytes per row per chunk
#define ROW_ULL      128            // HC*32 ull per row

typedef unsigned long long ull;

// scratch[hs][b][mat][k][d]  (fp32 partial sums over h-splits) : 25 MB
__device__ __align__(16) float g_scratch[(size_t)HSPLIT * BB * 3 * KK * DD];
// reduced logits (bias included): [b][mat][k][d] : 3 MB
__device__ __align__(16) float g_red[(size_t)BB * 3 * KK * DD];

#define RED_ELEMS4 (BB * 3 * KK * DD / 4)   // 196608 float4 outputs

// ---------------- PTX helpers ----------------
__device__ __forceinline__ void cp_async16(uint32_t dst, const void* src) {
    asm volatile("cp.async.ca.shared.global [%0], [%1], 16;\n" ::"r"(dst), "l"(src) : "memory");
}
__device__ __forceinline__ void cp_commit() {
    asm volatile("cp.async.commit_group;\n" ::: "memory");
}
template <int N>
__device__ __forceinline__ void cp_wait() {
    asm volatile("cp.async.wait_group %0;\n" ::"n"(N) : "memory");
}
// packed f32x2 FMA (Blackwell doubled-FP32 path; only reachable via PTX)
__device__ __forceinline__ void fma2(ull& d, ull a, ull b) {
    asm("fma.rn.f32x2 %0, %1, %2, %0;" : "+l"(d) : "l"(a), "l"(b));
}

// ---------------- Pass 1: 3x einsum bhd,khd->bkd (partial over h-split) ----------------
// smem chunk layout: [row 0..63][hh 0..3][d 0..63] floats (plain; 16B-contiguous in gmem)
//   rows 0..15  = x[bBase+row]
//   rows 16..63 = V{mat}[k] (mat-major: 16+mat*16+k)
// Per chunk: 4096 float4; thread (rg=tid>>6, colB=(tid&63)*16) covers rows rg+6i.
__device__ __forceinline__ void issue_chunk(
    uint32_t sbase, const char* const* rowPtr, int stage, int c, int rg, int colB)
{
    const uint32_t dstB = sbase + (uint32_t)stage * CHUNK_BYTES + (uint32_t)colB;
    const size_t so = (size_t)c * ROW_BYTES + (size_t)colB;
#pragma unroll
    for (int i = 0; i < 11; i++) {
        const int row = rg + 6 * i;
        if (i < 10 || rg < 4) {                 // rows 0..63 covered (rg 0..5)
            cp_async16(dstB + (uint32_t)row * 1024u, rowPtr[row] + so);
        }
    }
    cp_commit();
}

__global__ void __launch_bounds__(NTHREADS, 1) k_gemm(
    const float* __restrict__ x, const float* __restrict__ Va,
    const float* __restrict__ Vm, const float* __restrict__ Vs)
{
    extern __shared__ float sm[];
    __shared__ const char* rowPtr[64];
    const uint32_t sbase = (uint32_t)__cvta_generic_to_shared(sm);

    const int tid = threadIdx.x;
    const int w = tid >> 5;
    const int l = tid & 31;           // lane -> d-pair (d = 2l, 2l+1)
    const int bg  = w / 6;            // b-group 0..1 (8 b each)
    const int rem = w - bg * 6;
    const int mat = rem >> 1;         // 0=alpha 1=mu 2=sigma
    const int kh  = rem & 1;          // k-half 0..1 (8 k each)
    const int bBase = blockIdx.x * BT;
    const int h0Base = blockIdx.y * HRANGE;

    // Build per-CTA row pointer table (base of each smem row's gmem source at h0Base)
    if (tid < 64) {
        const int row = tid;
        const float* p;
        if (row < BT) {
            p = x + (size_t)(bBase + row) * (HH * DD) + (size_t)h0Base * DD;
        } else {
            const int r = row - BT;
            const int m = r >> 4;
            const int k = r & 15;
            const float* Vp = (m == 0) ? Va : ((m == 1) ? Vm : Vs);
            p = Vp + (size_t)k * (HH * DD) + (size_t)h0Base * DD;
        }
        rowPtr[row] = (const char*)p;
    }
    __syncthreads();

    const int rg   = tid >> 6;        // 0..5 (copy row group)
    const int colB = (tid & 63) * 16; // byte offset within row slab

    const int xrow0 = bg * 8;
    const int vrow0 = 16 + mat * 16 + kh * 8;

    ull acc[8][8];                    // [rb][kt] f32x2 accumulators (128 regs)
#pragma unroll
    for (int r = 0; r < 8; r++)
#pragma unroll
        for (int k = 0; k < 8; k++) acc[r][k] = 0ull;

    issue_chunk(sbase, rowPtr, 0, 0, rg, colB);
    issue_chunk(sbase, rowPtr, 1, 1, rg, colB);

    int stC = 0;                      // stage of chunk c
#pragma unroll 1
    for (int c = 0; c < NCHUNK; c++) {
        if (c + 1 < NCHUNK) { cp_wait<1>(); } else { cp_wait<0>(); }
        __syncthreads();                         // all warps done with chunk c-1's stage
        if (c + 2 < NCHUNK) {
            int stN = stC + 2; if (stN >= STAGES) stN -= STAGES;
            issue_chunk(sbase, rowPtr, stN, c + 2, rg, colB);  // safe: post-barrier
        }

        const ull* buf = (const ull*)sm + (size_t)stC * (CHUNK_FLOATS / 2);

#pragma unroll
        for (int hh = 0; hh < HC; hh++) {
            ull vv[8];
#pragma unroll
            for (int k = 0; k < 8; k++)
                vv[k] = buf[(vrow0 + k) * ROW_ULL + hh * 32 + l];
#pragma unroll
            for (int r = 0; r < 8; r++) {
                const ull xv = buf[(xrow0 + r) * ROW_ULL + hh * 32 + l];
#pragma unroll
                for (int k = 0; k < 8; k++) fma2(acc[r][k], xv, vv[k]);
            }
        }

        stC = stC + 1; if (stC == STAGES) stC = 0;
    }

    // store partials: scratch[hs][b][mat][k][d]
    ull* sc = (ull*)g_scratch;
    const int hs = blockIdx.y;
#pragma unroll
    for (int r = 0; r < 8; r++) {
        const int b = bBase + bg * 8 + r;
        const size_t base = ((((size_t)hs * BB + b) * 3 + mat) * KK + kh * 8) * 32;
#pragma unroll
        for (int k = 0; k < 8; k++)
            sc[base + (size_t)k * 32 + l] = acc[r][k];
    }
}

// ---------------- Pass 1.5: reduce over h-splits (+ bias) with full parallelism ----------------
__global__ void __launch_bounds__(256) k_reduce(
    const float* __restrict__ ba, const float* __restrict__ bm, const float* __restrict__ bs)
{
    const int idx = blockIdx.x * 256 + threadIdx.x;   // float4 index into g_red
    const float4* __restrict__ src = (const float4*)g_scratch;

    // flat layout: ((b*3 + mat)*16 + k)*16 + dq   (in float4 units)
    const int dq  = idx & 15;
    const int k   = (idx >> 4) & 15;
    const int mat = (idx >> 8) % 3;
    const float* bp = (mat == 0) ? ba : ((mat == 1) ? bm : bs);
    float4 s = ((const float4*)bp)[k * 16 + dq];

#pragma unroll
    for (int hs = 0; hs < HSPLIT; hs++) {
        const float4 v = src[(size_t)hs * RED_ELEMS4 + idx];
        s.x += v.x; s.y += v.y; s.z += v.z; s.w += v.w;
    }
    ((float4*)g_red)[idx] = s;
}

// ---------------- Pass 2: softmax/logsumexp epilogue, sum over d ----------------
__global__ void __launch_bounds__(256) k_final(
    const float* __restrict__ iv, float* __restrict__ out)
{
    const int tx = threadIdx.x;                    // lane -> d-pair
    const int b = blockIdx.x * 8 + threadIdx.y;    // one warp per b

    float2 ea[16], mu[16], ls[16];

    const float2* __restrict__ rd = (const float2*)g_red;
    const size_t base = ((size_t)b * 3) * 512 + tx;  // float2 units; mat stride 512, k stride 32
#pragma unroll
    for (int k = 0; k < 16; k++) ea[k] = rd[base + (size_t)k * 32];
#pragma unroll
    for (int k = 0; k < 16; k++) mu[k] = rd[base + 512 + (size_t)k * 32];
#pragma unroll
    for (int k = 0; k < 16; k++) ls[k] = rd[base + 1024 + (size_t)k * 32];

    const float2 y2 = ((const float2*)iv)[b * 32 + tx];

    float contrib = 0.f;
    const float HL2PI = 0.91893853320467274178f;
#pragma unroll
    for (int comp = 0; comp < 2; comp++) {
        const float yv = comp ? y2.y : y2.x;
        float mA = -3.0e38f;
#pragma unroll
        for (int k = 0; k < 16; k++) {
            const float e = comp ? ea[k].y : ea[k].x;
            mA = fmaxf(mA, e);
        }
        float sA = 0.f;
#pragma unroll
        for (int k = 0; k < 16; k++) {
            const float e = comp ? ea[k].y : ea[k].x;
            sA += __expf(e - mA);
        }
        const float lseA = mA + __logf(sA);

        float t[16];
        float mT = -3.0e38f;
#pragma unroll
        for (int k = 0; k < 16; k++) {
            const float e = comp ? ea[k].y : ea[k].x;
            const float m = comp ? mu[k].y : mu[k].x;
            float s = comp ? ls[k].y : ls[k].x;
            s = fminf(fmaxf(s, -20.f), 20.f);       // clip log_sigma
            const float z = (yv - m) * __expf(-s);
            const float tt = -0.5f * z * z + e - s;
            t[k] = tt;
            mT = fmaxf(mT, tt);
        }
        float sP = 0.f;
#pragma unroll
        for (int k = 0; k < 16; k++) sP += __expf(t[k] - mT);
        contrib += mT + __logf(sP) - lseA - HL2PI;
    }

    // warp reduction over d (32 lanes x 2 d each = 64 d)
#pragma unroll
    for (int off = 16; off > 0; off >>= 1)
        contrib += __shfl_down_sync(0xffffffffu, contrib, off);
    if (tx == 0) out[b] = contrib;
}

// ---------------- launch ----------------
extern "C" void kernel_launch(void* const* d_in, const int* in_sizes, int n_in,
                              void* d_out, int out_size)
{
    (void)in_sizes; (void)n_in; (void)out_size;
    const float* x  = (const float*)d_in[0];
    const float* iv = (const float*)d_in[1];
    const float* Va = (const float*)d_in[2];
    const float* Vm = (const float*)d_in[3];
    const float* Vs = (const float*)d_in[4];
    const float* ba = (const float*)d_in[5];
    const float* bm = (const float*)d_in[6];
    const float* bs = (const float*)d_in[7];

    const int smemBytes = STAGES * CHUNK_BYTES;  // 192 KB, 3-stage ring
    cudaFuncSetAttribute(k_gemm, cudaFuncAttributeMaxDynamicSharedMemorySize, smemBytes);

    k_gemm<<<dim3(BB / BT, HSPLIT), NTHREADS, smemBytes>>>(x, Va, Vm, Vs);
    k_reduce<<<RED_ELEMS4 / 256, 256>>>(ba, bm, bs);
    k_final<<<BB / 8, dim3(32, 8)>>>(iv, (float*)d_out);
}